// round 8
// baseline (speedup 1.0000x reference)
#include <cuda_runtime.h>
#include <cstdint>

// x:[4096,4096] f32, qweight:[4096,1376] i32 (8x int4 along O), scales:[32,11008] f32,
// qzeros:[32,1376] i32, out:[4096,11008] f32, group_size=128.
// tf32 mma.sync GEMM. Pair-layout SMEM images: (k, k+4) adjacent -> LDS.64 fragments.

#define I_DIM 4096
#define O_DIM 11008
#define OPACK 1376
#define BM 128
#define BN 256
#define BK 32
#define NITER 128
#define THREADS 256

#define A_WORDS (BM * BK)                 // 4096 words = 16KB image
#define B_WORDS (BN * BK)                 // 8192
#define STAGE_WORDS (A_WORDS + B_WORDS)   // 12288
#define SMEM_BYTES (2 * STAGE_WORDS * 4)  // 98304

// x pre-rounded to tf32, tiled as [rt(32)][kt(128)][4096-word SMEM images]
// image word(r,k) = r*32 + ((k>>3 ^ (r&3))<<3) + (k&3)*2 + ((k>>2)&1)
__device__ uint32_t g_xr[(size_t)32 * 128 * A_WORDS];

__device__ __forceinline__ uint32_t f2tf32(float f) {
    uint32_t u;
    asm("cvt.rna.tf32.f32 %0, %1;" : "=r"(u) : "f"(f));
    return u;
}

__device__ __forceinline__ uint32_t smem_u32(const void* p) {
    uint32_t a;
    asm("{ .reg .u64 t; cvta.to.shared.u64 t, %1; cvt.u32.u64 %0, t; }" : "=r"(a) : "l"(p));
    return a;
}

__device__ __forceinline__ void cp_async16(uint32_t dst, const void* src) {
    asm volatile("cp.async.cg.shared.global [%0], [%1], 16;" :: "r"(dst), "l"(src) : "memory");
}

__device__ __forceinline__ void mma_tf32(float* d, const uint32_t* a, const uint32_t* b) {
    asm volatile(
        "mma.sync.aligned.m16n8k8.row.col.f32.tf32.tf32.f32 "
        "{%0,%1,%2,%3},{%4,%5,%6,%7},{%8,%9},{%0,%1,%2,%3};"
        : "+f"(d[0]), "+f"(d[1]), "+f"(d[2]), "+f"(d[3])
        : "r"(a[0]), "r"(a[1]), "r"(a[2]), "r"(a[3]), "r"(b[0]), "r"(b[1]));
}

// ---- pre-kernel: round x to tf32, write pair-layout tile images ----
__global__ __launch_bounds__(256)
void round_x_kernel(const float4* __restrict__ x) {
    size_t idx = (size_t)blockIdx.x * 256 + threadIdx.x;   // over (r, k8): 4096*512
    int r  = (int)(idx >> 9);
    int k8 = (int)(idx & 511);
    float4 v0 = x[(size_t)r * 1024 + k8 * 2];
    float4 v1 = x[(size_t)r * 1024 + k8 * 2 + 1];
    // 8-word group order: (k&3)*2 + ((k>>2)&1) -> {k0,k4,k1,k5, k2,k6,k3,k7}
    uint4 u1, u2;
    u1.x = f2tf32(v0.x); u1.y = f2tf32(v1.x); u1.z = f2tf32(v0.y); u1.w = f2tf32(v1.y);
    u2.x = f2tf32(v0.z); u2.y = f2tf32(v1.z); u2.z = f2tf32(v0.w); u2.w = f2tf32(v1.w);
    int rt = r >> 7, rl = r & 127;
    int kt = k8 >> 2, oct = k8 & 3;
    uint32_t* dst = g_xr + (((size_t)rt * 128 + kt) << 12)
                  + rl * 32 + ((oct ^ (rl & 3)) << 3);
    *reinterpret_cast<uint4*>(dst)     = u1;
    *reinterpret_cast<uint4*>(dst + 4) = u2;
}

// ---- main GEMM ----
__global__ __launch_bounds__(THREADS, 1)
void q4_tf32_mma(const int* __restrict__ qweight,
                 const float* __restrict__ scales,
                 const int* __restrict__ qzeros,
                 float* __restrict__ out) {
    extern __shared__ uint32_t smem[];
    const uint32_t sbase = smem_u32(smem);

    const int tid  = threadIdx.x;
    const int lane = tid & 31;
    const int wid  = tid >> 5;
    const int gi   = lane >> 2;
    const int tq   = lane & 3;

    const int row0 = blockIdx.y * BM;
    const int col0 = blockIdx.x * BN;

    // 8 warps: 2 (M, 64) x 4 (N, 64)
    const int wm = wid & 1;
    const int wn = wid >> 1;

    // B loader: lane = ow (qweight col), warp id = kt (0..7)
    const int ow = tid & 31;
    const int kt = tid >> 5;
    const int bb = (kt & 3) | ((kt >> 2) << 3);   // pair-base row: {0..3, 8..11}
    const int*   qw_base = qweight + (col0 >> 3) + ow;
    const int*   qz_base = qzeros  + (col0 >> 3) + ow;
    const float* sc_base = scales  + col0 + ow * 8;

    const uint32_t* a_img = g_xr + (((size_t)(row0 >> 7)) * 128 << 12);

    uint32_t wS[4];
    uint32_t zS;
    float4 sS0, sS1;

    float acc[4][8][4];
#pragma unroll
    for (int mi = 0; mi < 4; mi++)
#pragma unroll
        for (int nb = 0; nb < 8; nb++)
#pragma unroll
            for (int j = 0; j < 4; j++) acc[mi][nb][j] = 0.0f;

    // A: identity cp.async of pre-built 16KB image
    auto issueA = [&](int it, int stage) {
        const uint32_t aB = sbase + stage * (STAGE_WORDS * 4);
        const uint32_t* src = a_img + ((size_t)it << 12);
#pragma unroll
        for (int j = 0; j < 4; j++) {
            int c = tid + j * 256;
            cp_async16(aB + c * 16, src + c * 4);
        }
        asm volatile("cp.async.commit_group;" ::: "memory");
    };

    auto loadB = [&](int it) {
        const int k0 = it * BK;
        wS[0] = (uint32_t)qw_base[(size_t)(k0 + bb)      * OPACK];
        wS[1] = (uint32_t)qw_base[(size_t)(k0 + bb + 4)  * OPACK];
        wS[2] = (uint32_t)qw_base[(size_t)(k0 + bb + 16) * OPACK];
        wS[3] = (uint32_t)qw_base[(size_t)(k0 + bb + 20) * OPACK];
        const int g = it >> 2;
        zS  = (uint32_t)qz_base[(size_t)g * OPACK];
        sS0 = *reinterpret_cast<const float4*>(sc_base + (size_t)g * O_DIM);
        sS1 = *reinterpret_cast<const float4*>(sc_base + (size_t)g * O_DIM + 4);
    };

    // B image word(n,k) = n*32 + ((k>>3 ^ (n&3) ^ ((n>>3)&3))<<3)
    //                    + ((k&3 ^ ((n>>5)&3))<<1) + ((k>>2)&1)
    auto storeB = [&](int stage) {
        uint32_t* Bs = smem + stage * STAGE_WORDS + A_WORDS;
        float sc[8] = {sS0.x, sS0.y, sS0.z, sS0.w, sS1.x, sS1.y, sS1.z, sS1.w};
        const int oct1 = bb >> 3;         // 0 or 1; second pair at oct1+2
        const int klo  = bb & 3;
#pragma unroll
        for (int o = 0; o < 8; o++) {
            float fz = __uint_as_float(0x4B000000u | ((zS >> (4 * o)) & 0xF));
            float d0 = (__uint_as_float(0x4B000000u | ((wS[0] >> (4 * o)) & 0xF)) - fz) * sc[o];
            float d1 = (__uint_as_float(0x4B000000u | ((wS[1] >> (4 * o)) & 0xF)) - fz) * sc[o];
            float d2 = (__uint_as_float(0x4B000000u | ((wS[2] >> (4 * o)) & 0xF)) - fz) * sc[o];
            float d3 = (__uint_as_float(0x4B000000u | ((wS[3] >> (4 * o)) & 0xF)) - fz) * sc[o];
            int n  = ow * 8 + o;
            int c0 = o & 3;               // n&3
            int c3 = ow & 3;              // (n>>3)&3
            int c5 = (ow >> 2) & 3;       // (n>>5)&3
            uint32_t base = n * 32 + ((oct1 ^ c0 ^ c3) << 3) + ((klo ^ c5) << 1);
            uint2 v1 = make_uint2(f2tf32(d0), f2tf32(d1));   // k=bb, bb+4
            uint2 v2 = make_uint2(f2tf32(d2), f2tf32(d3));   // k=bb+16, bb+20
            *reinterpret_cast<uint2*>(Bs + base)        = v1;
            *reinterpret_cast<uint2*>(Bs + (base ^ 16)) = v2;   // oct^2 -> word^16
        }
    };

    auto compute = [&](int stage) {
        const uint32_t* As = smem + stage * STAGE_WORDS;
        const uint32_t* Bs = As + A_WORDS;
#pragma unroll
        for (int kb = 0; kb < 4; kb++) {
            uint2 a[4][2];
#pragma unroll
            for (int mi = 0; mi < 4; mi++) {
                int R = wm * 64 + mi * 16 + gi;
                uint32_t off = R * 32 + (((kb ^ (gi & 3))) << 3) + tq * 2;
                a[mi][0] = *reinterpret_cast<const uint2*>(As + off);         // row R
                a[mi][1] = *reinterpret_cast<const uint2*>(As + off + 256);   // row R+8
            }
            uint2 b[8];
#pragma unroll
            for (int nb = 0; nb < 8; nb++) {
                int n = wn * 64 + nb * 8 + gi;
                uint32_t off = n * 32 + ((kb ^ (gi & 3) ^ ((wn * 8 + nb) & 3)) << 3)
                             + ((tq ^ ((wn * 2 + (nb >> 2)) & 3)) << 1);
                b[nb] = *reinterpret_cast<const uint2*>(Bs + off);
            }
#pragma unroll
            for (int mi = 0; mi < 4; mi++) {
                uint32_t av[4] = {a[mi][0].x, a[mi][1].x, a[mi][0].y, a[mi][1].y};
#pragma unroll
                for (int nb = 0; nb < 8; nb++)
                    mma_tf32(acc[mi][nb], av, &b[nb].x);
            }
        }
    };

    // ---------------- pipeline ----------------
    issueA(0, 0);
    loadB(0);
    asm volatile("cp.async.wait_group 0;" ::: "memory");
    storeB(0);
    __syncthreads();

    for (int it = 0; it < NITER; ++it) {
        const int s = it & 1;
        if (it + 1 < NITER) {
            issueA(it + 1, s ^ 1);
            loadB(it + 1);
        }
        compute(s);
        if (it + 1 < NITER) {
            asm volatile("cp.async.wait_group 0;" ::: "memory");
            storeB(s ^ 1);
        }
        __syncthreads();
    }

    // ---------------- epilogue ----------------
#pragma unroll
    for (int mi = 0; mi < 4; mi++) {
        int r = row0 + wm * 64 + mi * 16 + gi;
        float* o0 = out + (size_t)r * O_DIM + col0 + wn * 64;
        float* o1 = o0 + 8 * O_DIM;
#pragma unroll
        for (int nb = 0; nb < 8; nb++) {
            int c = nb * 8 + 2 * tq;
            *reinterpret_cast<float2*>(o0 + c) = make_float2(acc[mi][nb][0], acc[mi][nb][1]);
            *reinterpret_cast<float2*>(o1 + c) = make_float2(acc[mi][nb][2], acc[mi][nb][3]);
        }
    }
}

extern "C" void kernel_launch(void* const* d_in, const int* in_sizes, int n_in,
                              void* d_out, int out_size) {
    const float* x       = (const float*)d_in[0];
    const int*   qweight = (const int*)d_in[1];
    const float* scales  = (const float*)d_in[2];
    const int*   qzeros  = (const int*)d_in[3];
    float*       out     = (float*)d_out;

    static int configured = 0;
    if (!configured) {
        cudaFuncSetAttribute(q4_tf32_mma, cudaFuncAttributeMaxDynamicSharedMemorySize, SMEM_BYTES);
        configured = 1;
    }

    // 1) round + re-layout x into pair-layout tf32 images
    round_x_kernel<<<8192, 256>>>((const float4*)x);

    // 2) GEMM
    dim3 grid(O_DIM / BN, 4096 / BM);   // (43, 32)
    q4_tf32_mma<<<grid, THREADS, SMEM_BYTES>>>(qweight, scales, qzeros, out);
}

// round 9
// speedup vs baseline: 1.8950x; 1.8950x over previous
#include <cuda_runtime.h>
#include <cstdint>

// x:[4096,4096] f32, qweight:[4096,1376] i32 (8x int4 along O), scales:[32,11008] f32,
// qzeros:[32,1376] i32, out:[4096,11008] f32, group_size=128.
// fp16 mma.sync m16n8k16 GEMM (fp32 accum). x pre-rounded to fp16 tile images.

#define I_DIM 4096
#define O_DIM 11008
#define OPACK 1376
#define BM 128
#define BN 256
#define BK 64
#define NITER 64
#define THREADS 256

#define A_WORDS (BM * BK / 2)             // 4096 words (fp16x2) = 16KB image
#define B_WORDS (BN * BK / 2)             // 8192 words = 32KB
#define STAGE_WORDS (A_WORDS + B_WORDS)   // 12288
#define SMEM_BYTES (2 * STAGE_WORDS * 4)  // 98304

// x as fp16x2 tile images: [rt(32)][itk(64)][4096 words]
__device__ uint32_t g_xr[(size_t)32 * 64 * A_WORDS];

__device__ __forceinline__ uint32_t pack_f16x2(float lo, float hi) {
    uint32_t d;
    asm("cvt.rn.f16x2.f32 %0, %1, %2;" : "=r"(d) : "f"(hi), "f"(lo));
    return d;
}

__device__ __forceinline__ uint32_t smem_u32(const void* p) {
    uint32_t a;
    asm("{ .reg .u64 t; cvta.to.shared.u64 t, %1; cvt.u32.u64 %0, t; }" : "=r"(a) : "l"(p));
    return a;
}

__device__ __forceinline__ void cp_async16(uint32_t dst, const void* src) {
    asm volatile("cp.async.cg.shared.global [%0], [%1], 16;" :: "r"(dst), "l"(src) : "memory");
}

__device__ __forceinline__ void mma_f16(float* d, const uint32_t* a, const uint32_t* b) {
    asm volatile(
        "mma.sync.aligned.m16n8k16.row.col.f32.f16.f16.f32 "
        "{%0,%1,%2,%3},{%4,%5,%6,%7},{%8,%9},{%0,%1,%2,%3};"
        : "+f"(d[0]), "+f"(d[1]), "+f"(d[2]), "+f"(d[3])
        : "r"(a[0]), "r"(a[1]), "r"(a[2]), "r"(a[3]), "r"(b[0]), "r"(b[1]));
}

// ---- pre-kernel: x -> fp16 tile images ----
// image word(r,k2) = r*32 + ((chunk ^ ta(r))<<2) + (k2&3), chunk=k2>>2,
// ta(r) = ((r>>1)&3) | ((r&1)<<2)
__global__ __launch_bounds__(256)
void round_x_kernel(const float4* __restrict__ x) {
    size_t idx = (size_t)blockIdx.x * 256 + threadIdx.x;   // over 8-float chunks: 4096*512
    int r  = (int)(idx >> 9);
    int cg = (int)(idx & 511);
    float4 v0 = x[idx * 2];
    float4 v1 = x[idx * 2 + 1];
    uint4 u;
    u.x = pack_f16x2(v0.x, v0.y);
    u.y = pack_f16x2(v0.z, v0.w);
    u.z = pack_f16x2(v1.x, v1.y);
    u.w = pack_f16x2(v1.z, v1.w);
    int rt = r >> 7, rl = r & 127;
    int itk = cg >> 3, c = cg & 7;
    int ta = ((rl >> 1) & 3) | ((rl & 1) << 2);
    *reinterpret_cast<uint4*>(
        g_xr + (((size_t)rt * 64 + itk) << 12) + rl * 32 + ((c ^ ta) << 2)) = u;
}

// ---- main GEMM ----
__global__ __launch_bounds__(THREADS, 1)
void q4_f16_mma(const int* __restrict__ qweight,
                const float* __restrict__ scales,
                const int* __restrict__ qzeros,
                float* __restrict__ out) {
    extern __shared__ uint32_t smem[];
    const uint32_t sbase = smem_u32(smem);

    const int tid  = threadIdx.x;
    const int lane = tid & 31;
    const int wid  = tid >> 5;
    const int gi   = lane >> 2;
    const int tq   = lane & 3;

    const int row0 = blockIdx.y * BM;
    const int col0 = blockIdx.x * BN;

    // 8 warps: 2 (M, 64) x 4 (N, 64)
    const int wm = wid & 1;
    const int wn = wid >> 1;

    // B loader: lane = ow (qweight word col), warp = kt (k-octet 8*kt..8*kt+7)
    const int ow = tid & 31;
    const int kt = tid >> 5;
    const int*   qw_base = qweight + (col0 >> 3) + ow;
    const int*   qz_base = qzeros  + (col0 >> 3) + ow;
    const float* sc_base = scales  + col0 + ow * 8;

    const uint32_t* a_img = g_xr + (((size_t)(row0 >> 7)) * 64 << 12);

    uint32_t wS[8];
    uint32_t zS;
    float4 sS0, sS1;

    float acc[4][8][4];
#pragma unroll
    for (int mi = 0; mi < 4; mi++)
#pragma unroll
        for (int nb = 0; nb < 8; nb++)
#pragma unroll
            for (int j = 0; j < 4; j++) acc[mi][nb][j] = 0.0f;

    // A: identity cp.async of pre-built 16KB image (1024 x 16B chunks)
    auto issueA = [&](int it, int stage) {
        const uint32_t aB = sbase + stage * (STAGE_WORDS * 4);
        const uint32_t* src = a_img + ((size_t)it << 12);
#pragma unroll
        for (int j = 0; j < 4; j++) {
            int c = tid + j * 256;
            cp_async16(aB + c * 16, src + c * 4);
        }
        asm volatile("cp.async.commit_group;" ::: "memory");
    };

    auto loadB = [&](int it) {
        const int k0 = it * BK;
#pragma unroll
        for (int j = 0; j < 8; j++)
            wS[j] = (uint32_t)qw_base[(size_t)(k0 + kt * 8 + j) * OPACK];
        const int g = it >> 1;
        zS  = (uint32_t)qz_base[(size_t)g * OPACK];
        sS0 = *reinterpret_cast<const float4*>(sc_base + (size_t)g * O_DIM);
        sS1 = *reinterpret_cast<const float4*>(sc_base + (size_t)g * O_DIM + 4);
    };

    // B image word(n,k2) = n*32 + ((chunk ^ tb(n))<<2) + (k2&3)
    // tb(n) = (((n>>1)&3) | ((n&1)<<2)) ^ ((n>>3)&7)
    auto storeB = [&](int stage) {
        uint32_t* Bs = smem + stage * STAGE_WORDS + A_WORDS;
        float sc[8] = {sS0.x, sS0.y, sS0.z, sS0.w, sS1.x, sS1.y, sS1.z, sS1.w};
#pragma unroll
        for (int o = 0; o < 8; o++) {
            float fz = __uint_as_float(0x4B000000u | ((zS >> (4 * o)) & 0xF));
            float d[8];
#pragma unroll
            for (int j = 0; j < 8; j++) {
                float f = __uint_as_float(0x4B000000u | ((wS[j] >> (4 * o)) & 0xF));
                d[j] = (f - fz) * sc[o];   // exact integer diff, then scale
            }
            uint4 u;
            u.x = pack_f16x2(d[0], d[1]);
            u.y = pack_f16x2(d[2], d[3]);
            u.z = pack_f16x2(d[4], d[5]);
            u.w = pack_f16x2(d[6], d[7]);
            int n  = ow * 8 + o;
            int tb = (((o >> 1) & 3) | ((o & 1) << 2)) ^ (ow & 7);
            *reinterpret_cast<uint4*>(Bs + n * 32 + ((kt ^ tb) << 2)) = u;
        }
    };

    auto compute = [&](int stage) {
        const uint32_t* As = smem + stage * STAGE_WORDS;
        const uint32_t* Bs = As + A_WORDS;
        const int ta = ((gi >> 1) & 3) | ((gi & 1) << 2);
#pragma unroll
        for (int kb = 0; kb < 4; kb++) {
            uint32_t a[4][4];
#pragma unroll
            for (int mi = 0; mi < 4; mi++) {
                uint32_t base = (wm * 64 + mi * 16 + gi) * 32 + tq;
                uint32_t c0 = ((2 * kb) ^ ta) << 2;
                uint32_t c1 = ((2 * kb + 1) ^ ta) << 2;
                a[mi][0] = As[base + c0];
                a[mi][1] = As[base + 256 + c0];
                a[mi][2] = As[base + c1];
                a[mi][3] = As[base + 256 + c1];
            }
            uint32_t b[8][2];
#pragma unroll
            for (int nb = 0; nb < 8; nb++) {
                int n  = wn * 64 + nb * 8 + gi;
                int tb = ta ^ ((wn * 8 + nb) & 7);
                uint32_t base = n * 32 + tq;
                b[nb][0] = Bs[base + (((2 * kb) ^ tb) << 2)];
                b[nb][1] = Bs[base + (((2 * kb + 1) ^ tb) << 2)];
            }
#pragma unroll
            for (int mi = 0; mi < 4; mi++)
#pragma unroll
                for (int nb = 0; nb < 8; nb++)
                    mma_f16(acc[mi][nb], a[mi], b[nb]);
        }
    };

    // ---------------- pipeline ----------------
    issueA(0, 0);
    loadB(0);
    asm volatile("cp.async.wait_group 0;" ::: "memory");
    storeB(0);
    __syncthreads();

    for (int it = 0; it < NITER; ++it) {
        const int s = it & 1;
        if (it + 1 < NITER) {
            issueA(it + 1, s ^ 1);
            loadB(it + 1);
        }
        compute(s);
        if (it + 1 < NITER) {
            asm volatile("cp.async.wait_group 0;" ::: "memory");
            storeB(s ^ 1);
        }
        __syncthreads();
    }

    // ---------------- epilogue ----------------
#pragma unroll
    for (int mi = 0; mi < 4; mi++) {
        int r = row0 + wm * 64 + mi * 16 + gi;
        float* o0 = out + (size_t)r * O_DIM + col0 + wn * 64;
        float* o1 = o0 + 8 * O_DIM;
#pragma unroll
        for (int nb = 0; nb < 8; nb++) {
            int c = nb * 8 + 2 * tq;
            *reinterpret_cast<float2*>(o0 + c) = make_float2(acc[mi][nb][0], acc[mi][nb][1]);
            *reinterpret_cast<float2*>(o1 + c) = make_float2(acc[mi][nb][2], acc[mi][nb][3]);
        }
    }
}

extern "C" void kernel_launch(void* const* d_in, const int* in_sizes, int n_in,
                              void* d_out, int out_size) {
    const float* x       = (const float*)d_in[0];
    const int*   qweight = (const int*)d_in[1];
    const float* scales  = (const float*)d_in[2];
    const int*   qzeros  = (const int*)d_in[3];
    float*       out     = (float*)d_out;

    static int configured = 0;
    if (!configured) {
        cudaFuncSetAttribute(q4_f16_mma, cudaFuncAttributeMaxDynamicSharedMemorySize, SMEM_BYTES);
        configured = 1;
    }

    // 1) round x -> fp16 tile images (idempotent, capturable)
    round_x_kernel<<<8192, 256>>>((const float4*)x);

    // 2) GEMM
    dim3 grid(O_DIM / BN, 4096 / BM);   // (43, 32)
    q4_f16_mma<<<grid, THREADS, SMEM_BYTES>>>(qweight, scales, qzeros, out);
}

// round 10
// speedup vs baseline: 2.0060x; 1.0586x over previous
#include <cuda_runtime.h>
#include <cstdint>

// x:[4096,4096] f32, qweight:[4096,1376] i32 (8x int4 along O), scales:[32,11008] f32,
// qzeros:[32,1376] i32, out:[4096,11008] f32, group_size=128.
// fp16 mma.sync m16n8k16 GEMM (fp32 accum), fragments loaded via ldmatrix.x4.

#define I_DIM 4096
#define O_DIM 11008
#define OPACK 1376
#define BM 128
#define BN 256
#define BK 64
#define NITER 64
#define THREADS 256

#define A_WORDS (BM * BK / 2)             // 4096 words (fp16x2) = 16KB image
#define B_WORDS (BN * BK / 2)             // 8192 words = 32KB
#define STAGE_WORDS (A_WORDS + B_WORDS)   // 12288
#define SMEM_BYTES (2 * STAGE_WORDS * 4)  // 98304

// x as fp16x2 tile images: [rt(32)][itk(64)][4096 words]
__device__ uint32_t g_xr[(size_t)32 * 64 * A_WORDS];

__device__ __forceinline__ uint32_t pack_f16x2(float lo, float hi) {
    uint32_t d;
    asm("cvt.rn.f16x2.f32 %0, %1, %2;" : "=r"(d) : "f"(hi), "f"(lo));
    return d;
}

__device__ __forceinline__ uint32_t smem_u32(const void* p) {
    uint32_t a;
    asm("{ .reg .u64 t; cvta.to.shared.u64 t, %1; cvt.u32.u64 %0, t; }" : "=r"(a) : "l"(p));
    return a;
}

__device__ __forceinline__ void cp_async16(uint32_t dst, const void* src) {
    asm volatile("cp.async.cg.shared.global [%0], [%1], 16;" :: "r"(dst), "l"(src) : "memory");
}

__device__ __forceinline__ void ldmatrix_x4(uint32_t* r, uint32_t addr) {
    asm volatile("ldmatrix.sync.aligned.m8n8.x4.shared.b16 {%0,%1,%2,%3}, [%4];"
                 : "=r"(r[0]), "=r"(r[1]), "=r"(r[2]), "=r"(r[3]) : "r"(addr));
}

__device__ __forceinline__ void mma_f16(float* d, const uint32_t* a, const uint32_t* b) {
    asm volatile(
        "mma.sync.aligned.m16n8k16.row.col.f32.f16.f16.f32 "
        "{%0,%1,%2,%3},{%4,%5,%6,%7},{%8,%9},{%0,%1,%2,%3};"
        : "+f"(d[0]), "+f"(d[1]), "+f"(d[2]), "+f"(d[3])
        : "r"(a[0]), "r"(a[1]), "r"(a[2]), "r"(a[3]), "r"(b[0]), "r"(b[1]));
}

// ---- pre-kernel: x -> fp16 tile images ----
// image word(r,k2) = r*32 + ((chunk ^ ta(r))<<2) + (k2&3), chunk=k2>>2,
// ta(r) = ((r>>1)&3) | ((r&1)<<2)
__global__ __launch_bounds__(256)
void round_x_kernel(const float4* __restrict__ x) {
    size_t idx = (size_t)blockIdx.x * 256 + threadIdx.x;   // over 8-float chunks
    int r  = (int)(idx >> 9);
    int cg = (int)(idx & 511);
    float4 v0 = x[idx * 2];
    float4 v1 = x[idx * 2 + 1];
    uint4 u;
    u.x = pack_f16x2(v0.x, v0.y);
    u.y = pack_f16x2(v0.z, v0.w);
    u.z = pack_f16x2(v1.x, v1.y);
    u.w = pack_f16x2(v1.z, v1.w);
    int rt = r >> 7, rl = r & 127;
    int itk = cg >> 3, c = cg & 7;
    int ta = ((rl >> 1) & 3) | ((rl & 1) << 2);
    *reinterpret_cast<uint4*>(
        g_xr + (((size_t)rt * 64 + itk) << 12) + rl * 32 + ((c ^ ta) << 2)) = u;
}

// ---- main GEMM ----
__global__ __launch_bounds__(THREADS, 1)
void q4_f16_mma(const int* __restrict__ qweight,
                const float* __restrict__ scales,
                const int* __restrict__ qzeros,
                float* __restrict__ out) {
    extern __shared__ uint32_t smem[];
    const uint32_t sbase = smem_u32(smem);

    const int tid  = threadIdx.x;
    const int lane = tid & 31;
    const int wid  = tid >> 5;
    const int gi   = lane >> 2;
    const int tq   = lane & 3;

    const int row0 = blockIdx.y * BM;
    const int col0 = blockIdx.x * BN;

    // 8 warps: 2 (M, 64) x 4 (N, 64)
    const int wm = wid & 1;
    const int wn = wid >> 1;

    // ldmatrix lane roles
    const int lj = lane & 7;        // row within 8x8 matrix
    const int lg = lane >> 3;       // matrix group 0..3
    const int ta_l = ((lj >> 1) & 3) | ((lj & 1) << 2);
    // A: reg g -> (m + (g&1)*8, chunk c0/c1 by g>>1)
    const int a_csel = lg >> 1;
    uint32_t a_row_byte[4];
#pragma unroll
    for (int mi = 0; mi < 4; mi++)
        a_row_byte[mi] = (uint32_t)(wm * 64 + mi * 16 + ((lg & 1) << 3) + lj) * 128;
    // B: pair p -> regs {b[2p][0], b[2p][1], b[2p+1][0], b[2p+1][1]}
    const int b_csel = lg & 1;
    uint32_t b_row_byte[4];
    int tb_l[4];
#pragma unroll
    for (int p = 0; p < 4; p++) {
        int nhi = wn * 8 + 2 * p + (lg >> 1);   // n>>3
        b_row_byte[p] = (uint32_t)(nhi * 8 + lj) * 128;
        tb_l[p] = ta_l ^ (nhi & 7);
    }

    // B loader: lane = ow (qweight word col), warp = kt (k-octet)
    const int ow = tid & 31;
    const int kt = tid >> 5;
    const int*   qw_base = qweight + (col0 >> 3) + ow;
    const int*   qz_base = qzeros  + (col0 >> 3) + ow;
    const float* sc_base = scales  + col0 + ow * 8;

    const uint32_t* a_img = g_xr + (((size_t)(row0 >> 7)) * 64 << 12);

    uint32_t wS[8];
    uint32_t zS;
    float4 sS0, sS1;

    float acc[4][8][4];
#pragma unroll
    for (int mi = 0; mi < 4; mi++)
#pragma unroll
        for (int nb = 0; nb < 8; nb++)
#pragma unroll
            for (int j = 0; j < 4; j++) acc[mi][nb][j] = 0.0f;

    auto issueA = [&](int it, int stage) {
        const uint32_t aB = sbase + stage * (STAGE_WORDS * 4);
        const uint32_t* src = a_img + ((size_t)it << 12);
#pragma unroll
        for (int j = 0; j < 4; j++) {
            int c = tid + j * 256;
            cp_async16(aB + c * 16, src + c * 4);
        }
        asm volatile("cp.async.commit_group;" ::: "memory");
    };

    auto loadB = [&](int it) {
        const int k0 = it * BK;
#pragma unroll
        for (int j = 0; j < 8; j++)
            wS[j] = (uint32_t)qw_base[(size_t)(k0 + kt * 8 + j) * OPACK];
        const int g = it >> 1;
        zS  = (uint32_t)qz_base[(size_t)g * OPACK];
        sS0 = *reinterpret_cast<const float4*>(sc_base + (size_t)g * O_DIM);
        sS1 = *reinterpret_cast<const float4*>(sc_base + (size_t)g * O_DIM + 4);
    };

    // B image word(n,k2) = n*32 + ((chunk ^ tb(n))<<2) + (k2&3)
    // tb(n) = ta(n&7) ^ ((n>>3)&7)
    auto storeB = [&](int stage) {
        uint32_t* Bs = smem + stage * STAGE_WORDS + A_WORDS;
        float sc[8] = {sS0.x, sS0.y, sS0.z, sS0.w, sS1.x, sS1.y, sS1.z, sS1.w};
#pragma unroll
        for (int o = 0; o < 8; o++) {
            float fz = __uint_as_float(0x4B000000u | ((zS >> (4 * o)) & 0xF));
            float d[8];
#pragma unroll
            for (int j = 0; j < 8; j++) {
                float f = __uint_as_float(0x4B000000u | ((wS[j] >> (4 * o)) & 0xF));
                d[j] = (f - fz) * sc[o];
            }
            uint4 u;
            u.x = pack_f16x2(d[0], d[1]);
            u.y = pack_f16x2(d[2], d[3]);
            u.z = pack_f16x2(d[4], d[5]);
            u.w = pack_f16x2(d[6], d[7]);
            int n  = ow * 8 + o;
            int tb = (((o >> 1) & 3) | ((o & 1) << 2)) ^ (ow & 7);
            *reinterpret_cast<uint4*>(Bs + n * 32 + ((kt ^ tb) << 2)) = u;
        }
    };

    auto compute = [&](int stage) {
        const uint32_t aB = sbase + stage * (STAGE_WORDS * 4);
        const uint32_t bB = aB + A_WORDS * 4;
#pragma unroll
        for (int kb = 0; kb < 4; kb++) {
            uint32_t a[4][4];
#pragma unroll
            for (int mi = 0; mi < 4; mi++)
                ldmatrix_x4(a[mi], aB + a_row_byte[mi]
                            + ((uint32_t)((2 * kb + a_csel) ^ ta_l) << 4));
            uint32_t b[4][4];
#pragma unroll
            for (int p = 0; p < 4; p++)
                ldmatrix_x4(b[p], bB + b_row_byte[p]
                            + ((uint32_t)((2 * kb + b_csel) ^ tb_l[p]) << 4));
#pragma unroll
            for (int mi = 0; mi < 4; mi++)
#pragma unroll
                for (int nb = 0; nb < 8; nb++)
                    mma_f16(acc[mi][nb], a[mi], &b[nb >> 1][(nb & 1) * 2]);
        }
    };

    // ---------------- pipeline ----------------
    issueA(0, 0);
    loadB(0);
    asm volatile("cp.async.wait_group 0;" ::: "memory");
    storeB(0);
    __syncthreads();

    for (int it = 0; it < NITER; ++it) {
        const int s = it & 1;
        if (it + 1 < NITER) {
            issueA(it + 1, s ^ 1);
            loadB(it + 1);
        }
        compute(s);
        if (it + 1 < NITER) {
            asm volatile("cp.async.wait_group 0;" ::: "memory");
            storeB(s ^ 1);
        }
        __syncthreads();
    }

    // ---------------- epilogue ----------------
#pragma unroll
    for (int mi = 0; mi < 4; mi++) {
        int r = row0 + wm * 64 + mi * 16 + gi;
        float* o0 = out + (size_t)r * O_DIM + col0 + wn * 64;
        float* o1 = o0 + 8 * O_DIM;
#pragma unroll
        for (int nb = 0; nb < 8; nb++) {
            int c = nb * 8 + 2 * tq;
            *reinterpret_cast<float2*>(o0 + c) = make_float2(acc[mi][nb][0], acc[mi][nb][1]);
            *reinterpret_cast<float2*>(o1 + c) = make_float2(acc[mi][nb][2], acc[mi][nb][3]);
        }
    }
}

extern "C" void kernel_launch(void* const* d_in, const int* in_sizes, int n_in,
                              void* d_out, int out_size) {
    const float* x       = (const float*)d_in[0];
    const int*   qweight = (const int*)d_in[1];
    const float* scales  = (const float*)d_in[2];
    const int*   qzeros  = (const int*)d_in[3];
    float*       out     = (float*)d_out;

    static int configured = 0;
    if (!configured) {
        cudaFuncSetAttribute(q4_f16_mma, cudaFuncAttributeMaxDynamicSharedMemorySize, SMEM_BYTES);
        configured = 1;
    }

    // 1) round x -> fp16 tile images (idempotent, capturable)
    round_x_kernel<<<8192, 256>>>((const float4*)x);

    // 2) GEMM
    dim3 grid(O_DIM / BN, 4096 / BM);   // (43, 32)
    q4_f16_mma<<<grid, THREADS, SMEM_BYTES>>>(qweight, scales, qzeros, out);
}